// round 13
// baseline (speedup 1.0000x reference)
#include <cuda_runtime.h>
#include <math.h>

#define MU   0.02f
#define MU2  (0.02f * 0.02f)
#define NBINS 10
#define MAXN  4194304
#define GRID_A 2048
#define GRID_B 1024          // divides 2^32 -> modulo completion counter is replay-safe
#define TPB   256
#define FLT_MAX_C __uint_as_float(0x7F7FFFFFu)

// Static device scratch. NO init kernel: every word written each launch,
// except g_done which is monotonic (modulo detection).
__device__ float2       gl_buf[MAXN];            // per row: (g, loss)
__device__ float        g_blkmin[GRID_A];        // per-passA-block min of g
__device__ float        g_blkmax[GRID_A];        // per-passA-block max of g
__device__ int          g_blk_cnt[NBINS][GRID_B];// per-passB-block bin counts
__device__ float        g_blk_sum[NBINS][GRID_B];// per-passB-block bin loss sums
__device__ unsigned int g_done;                  // monotonic completion counter

// ---------------------------------------------------------------------------
// Pass A: per-row loss & g (fast math: rsqrtf), store interleaved,
// per-block min/max of g to private slots (no atomics, no init).
__global__ __launch_bounds__(TPB) void passA_kernel(
    const float4* __restrict__ inp, const float4* __restrict__ tgt, int N)
{
    const int stride = GRID_A * TPB;
    float lmin = FLT_MAX_C;
    float lmax = 0.0f;

#pragma unroll 2
    for (int i = blockIdx.x * TPB + threadIdx.x; i < N; i += stride) {
        float4 a = __ldcs(&inp[i]);
        float4 b = __ldcs(&tgt[i]);
        float d0 = a.x - b.x, d1 = a.y - b.y, d2 = a.z - b.z, d3 = a.w - b.w;
        float x0 = fmaf(d0, d0, MU2), x1 = fmaf(d1, d1, MU2);
        float x2 = fmaf(d2, d2, MU2), x3 = fmaf(d3, d3, MU2);
        float r0 = rsqrtf(x0), r1 = rsqrtf(x1), r2 = rsqrtf(x2), r3 = rsqrtf(x3);
        float e0 = x0 * r0, e1 = x1 * r1, e2 = x2 * r2, e3 = x3 * r3;  // ~sqrt
        float loss = (e0 - MU) + (e1 - MU) + (e2 - MU) + (e3 - MU);
        float g = fabsf(d0) * r0 + fabsf(d1) * r1
                + fabsf(d2) * r2 + fabsf(d3) * r3;

        __stcg(&gl_buf[i], make_float2(g, loss));   // keep in L2 for pass B
        lmin = fminf(lmin, g);
        lmax = fmaxf(lmax, g);
    }

    // warp reduce min/max
    for (int off = 16; off > 0; off >>= 1) {
        lmin = fminf(lmin, __shfl_down_sync(0xFFFFFFFFu, lmin, off));
        lmax = fmaxf(lmax, __shfl_down_sync(0xFFFFFFFFu, lmax, off));
    }
    __shared__ float smin[TPB / 32], smax[TPB / 32];
    int wid = threadIdx.x >> 5, lid = threadIdx.x & 31;
    if (lid == 0) { smin[wid] = lmin; smax[wid] = lmax; }
    __syncthreads();
    if (wid == 0) {
        lmin = (lid < TPB / 32) ? smin[lid] : FLT_MAX_C;
        lmax = (lid < TPB / 32) ? smax[lid] : 0.0f;
        for (int off = 4; off > 0; off >>= 1) {
            lmin = fminf(lmin, __shfl_down_sync(0xFFFFFFFFu, lmin, off));
            lmax = fmaxf(lmax, __shfl_down_sync(0xFFFFFFFFu, lmax, off));
        }
        if (lid == 0) {
            g_blkmin[blockIdx.x] = lmin;   // plain slot store: no init needed
            g_blkmax[blockIdx.x] = lmax;
        }
    }
}

// ---------------------------------------------------------------------------
// Bin exactly as the reference: clip(floor((g / range) * 10), 0, 9)
__device__ __forceinline__ int bin_of(float g, float range) {
    int b = __float2int_rd(__fmul_rn(__fdiv_rn(g, range), 10.0f));
    return max(0, min(NBINS - 1, b));
}

// ---------------------------------------------------------------------------
// Pass B: reduce block min/max -> range; histogram with per-thread local
// arrays; per-block partials to slots; last block (modulo counter) finalizes.
__global__ __launch_bounds__(TPB) void passB_kernel(float* __restrict__ out, int N)
{
    const int tid = threadIdx.x;
    const int wid = tid >> 5, lid = tid & 31;

    // --- 1) global min/max from passA block slots (each block redundantly) ---
    float lmin = FLT_MAX_C, lmax = 0.0f;
    for (int i = tid; i < GRID_A; i += TPB) {
        lmin = fminf(lmin, g_blkmin[i]);
        lmax = fmaxf(lmax, g_blkmax[i]);
    }
    for (int off = 16; off > 0; off >>= 1) {
        lmin = fminf(lmin, __shfl_down_sync(0xFFFFFFFFu, lmin, off));
        lmax = fmaxf(lmax, __shfl_down_sync(0xFFFFFFFFu, lmax, off));
    }
    __shared__ float smm[2][TPB / 32];
    if (lid == 0) { smm[0][wid] = lmin; smm[1][wid] = lmax; }
    __syncthreads();
    __shared__ float s_range;
    if (tid == 0) {
        float m0 = smm[0][0], m1 = smm[1][0];
        for (int w = 1; w < TPB / 32; w++) {
            m0 = fminf(m0, smm[0][w]);
            m1 = fmaxf(m1, smm[1][w]);
        }
        s_range = __fsub_rn(m1, m0);
    }
    __syncthreads();
    const float range = s_range;

    // --- 2) histogram: contention-free per-thread local bins ---
    float lsum[NBINS];
    int   lcnt[NBINS];
#pragma unroll
    for (int b = 0; b < NBINS; b++) { lsum[b] = 0.0f; lcnt[b] = 0; }

    const int gtid = blockIdx.x * TPB + tid;
    const int gstride = GRID_B * TPB;
    const int N2 = N >> 1;
    const float4* gl4 = (const float4*)gl_buf;   // two rows per float4
    for (int i = gtid; i < N2; i += gstride) {
        float4 v = __ldcg(&gl4[i]);
        int b0 = bin_of(v.x, range);
        lsum[b0] += v.y; lcnt[b0] += 1;
        int b1 = bin_of(v.z, range);
        lsum[b1] += v.w; lcnt[b1] += 1;
    }
    for (int i = (N2 << 1) + gtid; i < N; i += gstride) {   // tail (odd N)
        float2 v = __ldcg(&gl_buf[i]);
        int b = bin_of(v.x, range);
        lsum[b] += v.y; lcnt[b] += 1;
    }

    // --- 3) deterministic fixed-order block reduce -> per-block slot ---
    __shared__ float ssum[NBINS][TPB];
    __shared__ int   scnt[NBINS][TPB];
#pragma unroll
    for (int b = 0; b < NBINS; b++) {
        ssum[b][tid] = lsum[b];
        scnt[b][tid] = lcnt[b];
    }
    __syncthreads();
    __shared__ float s2sum[NBINS][8];
    __shared__ int   s2cnt[NBINS][8];
    if (tid < NBINS * 8) {
        int b = tid >> 3, c = tid & 7;
        float fs = 0.0f; int ic = 0;
        int base = c * 32;
        for (int j = 0; j < 32; j++) { fs += ssum[b][base + j]; ic += scnt[b][base + j]; }
        s2sum[b][c] = fs; s2cnt[b][c] = ic;
    }
    __syncthreads();
    if (tid < NBINS) {
        int b = tid;
        float fs = 0.0f; int ic = 0;
        for (int c = 0; c < 8; c++) { fs += s2sum[b][c]; ic += s2cnt[b][c]; }
        g_blk_sum[b][blockIdx.x] = fs;    // plain slot store
        g_blk_cnt[b][blockIdx.x] = ic;
    }

    // --- 4) last-block finalize (monotonic counter, replay-safe modulo) ---
    __shared__ unsigned int is_last;
    __threadfence();                      // release slot stores
    __syncthreads();
    if (tid == 0) {
        unsigned int old = atomicAdd(&g_done, 1u);
        is_last = (((old + 1u) & (GRID_B - 1u)) == 0u) ? 1u : 0u;
    }
    __syncthreads();
    if (is_last) {
        __threadfence();                  // acquire
        __shared__ float fbin_sum[NBINS];
        __shared__ int   fbin_cnt[NBINS];
        // warp wid handles bins wid, wid+8 (fixed partition & tree: deterministic)
        for (int b = wid; b < NBINS; b += TPB / 32) {
            float fs = 0.0f; int ic = 0;
            for (int i = lid; i < GRID_B; i += 32) {
                fs += __ldcg(&g_blk_sum[b][i]);
                ic += __ldcg(&g_blk_cnt[b][i]);
            }
            for (int off = 16; off > 0; off >>= 1) {
                fs += __shfl_down_sync(0xFFFFFFFFu, fs, off);
                ic += __shfl_down_sync(0xFFFFFFFFu, ic, off);
            }
            if (lid == 0) { fbin_sum[b] = fs; fbin_cnt[b] = ic; }
        }
        __syncthreads();
        if (tid == 0) {
            double acc = 0.0;
            int n = 0;
            for (int b = 0; b < NBINS; b++) {
                int c = fbin_cnt[b];
                if (c > 0) { n++; acc += (double)fbin_sum[b] / (double)c; }
            }
            if (n < 1) n = 1;
            out[0] = (float)(acc / (double)n / 64.0 / 4096.0);
        }
    }
}

// ---------------------------------------------------------------------------
extern "C" void kernel_launch(void* const* d_in, const int* in_sizes, int n_in,
                              void* d_out, int out_size)
{
    const float4* inp = (const float4*)d_in[0];
    const float4* tgt = (const float4*)d_in[1];
    float* out = (float*)d_out;
    int N = in_sizes[0] / 4;   // rows (C = 4 floats per row)
    if (N > MAXN) N = MAXN;

    passA_kernel<<<GRID_A, TPB>>>(inp, tgt, N);
    passB_kernel<<<GRID_B, TPB>>>(out, N);
}